// round 11
// baseline (speedup 1.0000x reference)
#include <cuda_runtime.h>
#include <math.h>
#include <stdint.h>

// Problem constants
#define NQ     512
#define NROWS  4096
#define VPR    256
#define DIM    128
#define KSEL   32
#define RCAP   256

// Output layout (flat float32 concat, reference tuple order)
#define OFF_VAL   0LL
#define OFF_ENT   2097152LL
#define OFF_GID   2113536LL
#define OFF_SC    2129920LL
#define OFF_MASK  2146304LL
#define OFF_NDIS  2162688LL
#define OFF_ATTN  2162689LL

// ---------------------------------------------------------------------------
// helpers
// ---------------------------------------------------------------------------
__device__ __forceinline__ uint32_t smem_u32(const void* p) {
    uint32_t a;
    asm("{ .reg .u64 t; cvta.to.shared.u64 t, %1; cvt.u32.u64 %0, t; }" : "=r"(a) : "l"(p));
    return a;
}

#define LDSM_X4(r0, r1, r2, r3, addr) \
    asm volatile("ldmatrix.sync.aligned.m8n8.x4.shared.b16 {%0,%1,%2,%3}, [%4];" \
        : "=r"(r0), "=r"(r1), "=r"(r2), "=r"(r3) : "r"(addr))

#define MMA16816(d, a, b) \
    asm volatile("mma.sync.aligned.m16n8k16.row.col.f32.bf16.bf16.f32 " \
        "{%0,%1,%2,%3}, {%4,%5,%6,%7}, {%8,%9}, {%0,%1,%2,%3};" \
        : "+f"((d)[0]), "+f"((d)[1]), "+f"((d)[2]), "+f"((d)[3]) \
        : "r"((a)[0]), "r"((a)[1]), "r"((a)[2]), "r"((a)[3]), \
          "r"((b)[0]), "r"((b)[1]))

__device__ __forceinline__ uint32_t pack_bf16x2(float lo, float hi) {
    uint32_t r;
    asm("cvt.rn.bf16x2.f32 %0, %1, %2;" : "=r"(r) : "f"(hi), "f"(lo));
    return r;
}

__device__ __forceinline__ uint32_t ford(float s) {
    uint32_t u = __float_as_uint(s);
    return (u & 0x80000000u) ? ~u : (u | 0x80000000u);
}
__device__ __forceinline__ float funord(uint32_t u) {
    return (u & 0x80000000u) ? __uint_as_float(u & 0x7FFFFFFFu) : __uint_as_float(~u);
}

#define MBARRIER_INIT(mb, cnt) \
    asm volatile("mbarrier.init.shared.b64 [%0], %1;" :: "r"((uint32_t)(mb)), "r"((uint32_t)(cnt)) : "memory")
#define MBARRIER_EXPECT_TX(mb, bytes) \
    asm volatile("mbarrier.arrive.expect_tx.shared.b64 _, [%0], %1;" :: "r"((uint32_t)(mb)), "r"((uint32_t)(bytes)) : "memory")
#define MBARRIER_ARRIVE(mb) \
    asm volatile("mbarrier.arrive.shared.b64 _, [%0];" :: "r"((uint32_t)(mb)) : "memory")
#define MBARRIER_WAIT_PARITY(mb, par) do { \
    uint32_t _mb = (uint32_t)(mb); uint32_t _pa = (uint32_t)(par); uint32_t _dn; \
    asm volatile("{\n\t.reg .pred p;\n\tmbarrier.try_wait.parity.acquire.cta.shared::cta.b64 p, [%1], %2;\n\tselp.b32 %0, 1, 0, p;\n\t}" \
        : "=r"(_dn) : "r"(_mb), "r"(_pa) : "memory"); \
    if (!_dn) { \
        asm volatile("{\n\t.reg .pred P1;\n\tWL_%=:\n\tmbarrier.try_wait.parity.acquire.cta.shared::cta.b64 P1, [%0], %1, 0x989680;\n\t@P1 bra.uni WD_%=;\n\tbra.uni WL_%=;\n\tWD_%=:\n\t}" \
            :: "r"(_mb), "r"(_pa) : "memory"); \
    } \
} while (0)
#define NAMED_BAR(id, cnt) \
    asm volatile("bar.sync %0, %1;" :: "r"(id), "r"(cnt) : "memory")

__device__ __forceinline__ void bulk_g2s(uint32_t dst, const void* src, uint32_t bytes, uint32_t mbar) {
    asm volatile("cp.async.bulk.shared::cluster.global.mbarrier::complete_tx::bytes [%0], [%1], %2, [%3];"
        :: "r"(dst), "l"(src), "r"(bytes), "r"(mbar) : "memory");
}

// ---------------------------------------------------------------------------
// Scratch
// ---------------------------------------------------------------------------
__device__ float g_rowmax[(size_t)NQ*NROWS];
__device__ int   g_cand[(size_t)NQ*RCAP];
__device__ int   g_qcnt[NQ];
__device__ int   g_rowcnt[NROWS];
__device__ int   g_rowlist[(size_t)NROWS*NQ];
__device__ float g_exs2[(size_t)NQ*RCAP*2];
__device__ int   g_exa2[(size_t)NQ*RCAP*2];
__device__ int   g_qdis[NQ];

// ---------------------------------------------------------------------------
// Pass A: approx scores (1-term bf16 HMMA), warp-specialized.
// 320 threads: warps 0-7 MMA consumers, warps 8-9 convert producers.
// Tile M=128 q x N=64 keys x K=128. 148 CTAs (one wave).
// smem: Q bf16 32KB | B bf16 2x16KB | fp32 staging 2x32KB = 128KB dynamic.
// ---------------------------------------------------------------------------
#define GROUPS   37
#define BBUF_OFF 32768
#define STG_OFF  65536
#define SMEM_A   131072

__global__ void __launch_bounds__(320, 1)
score_approx(const float* __restrict__ queries, const float* __restrict__ keys)
{
    extern __shared__ __align__(1024) char sm[];
    const uint32_t sb = smem_u32(sm);
    __shared__ float xv[2][128];
    __shared__ unsigned long long s_bars[6];   // dma[2], full[2], empty[2]

    const int tid  = threadIdx.x;
    const int wid  = tid >> 5;
    const int lane = tid & 31;
    const int qt   = blockIdx.x & 3;
    const int rg   = blockIdx.x >> 2;
    const int q0   = qt * 128;

    const uint32_t dmab0  = smem_u32(&s_bars[0]);
    const uint32_t dmab1  = smem_u32(&s_bars[1]);
    const uint32_t fullb0 = smem_u32(&s_bars[2]);
    const uint32_t fullb1 = smem_u32(&s_bars[3]);
    const uint32_t emptb0 = smem_u32(&s_bars[4]);
    const uint32_t emptb1 = smem_u32(&s_bars[5]);

    if (tid == 0) {
        MBARRIER_INIT(dmab0, 1);  MBARRIER_INIT(dmab1, 1);
        MBARRIER_INIT(fullb0, 64); MBARRIER_INIT(fullb1, 64);
        MBARRIER_INIT(emptb0, 256); MBARRIER_INIT(emptb1, 256);
    }
    __syncthreads();

    const int nrows = (NROWS - rg + GROUPS - 1) / GROUPS;
    const int NT = nrows * 4;

    // issue DMA for tiles 0 and 1
    if (tid == 256) {
        MBARRIER_EXPECT_TX(dmab0, 32768);
        bulk_g2s(sb + STG_OFF, keys + (size_t)rg * VPR * DIM, 32768, dmab0);
        if (NT > 1) {
            MBARRIER_EXPECT_TX(dmab1, 32768);
            bulk_g2s(sb + STG_OFF + 32768,
                     keys + ((size_t)rg * VPR + 64) * DIM, 32768, dmab1);
        }
    }

    // ---- Q prologue (threads 0-255): fp32 -> bf16 -> swizzled smem ----
    if (tid < 256) {
        int q = tid >> 1, h = tid & 1;
        const float4* qp = reinterpret_cast<const float4*>(
            queries + (size_t)(q0 + q) * DIM + h * 64);
        #pragma unroll
        for (int jj = 0; jj < 8; ++jj) {
            float4 x = qp[2*jj], y = qp[2*jj+1];
            uint4 s0;
            s0.x = pack_bf16x2(x.x, x.y);
            s0.y = pack_bf16x2(x.z, x.w);
            s0.z = pack_bf16x2(y.x, y.y);
            s0.w = pack_bf16x2(y.z, y.w);
            int cb = h * 8 + jj;
            uint32_t o = (uint32_t)q * 256u + (uint32_t)((cb ^ (q & 7)) << 4);
            *reinterpret_cast<uint4*>(sm + o) = s0;
        }
    }
    __syncthreads();

    if (tid >= 256) {
        // ================= producer: convert warps (64 threads) =================
        const int ctid = tid - 256;            // 0..63, one key per thread
        const uint32_t drow = (uint32_t)ctid * 256u;
        const uint32_t dxor = (uint32_t)(ctid & 7);
        for (int t = 0; t < NT; ++t) {
            const int u = t >> 1, s = t & 1;
            const uint32_t dmab = s ? dmab1 : dmab0;
            MBARRIER_WAIT_PARITY(dmab, u & 1);
            if (t >= 2) MBARRIER_WAIT_PARITY(s ? emptb1 : emptb0, (u + 1) & 1);

            const float4* stg = reinterpret_cast<const float4*>(sm + STG_OFF + s * 32768);
            char* bb = sm + BBUF_OFF + s * 16384;
            #pragma unroll 8
            for (int j0 = 0; j0 < 32; ++j0) {
                int f = (j0 + ctid) & 31;      // bank-rotated staging read
                float4 v = stg[ctid * 32 + f];
                uint2 pr;
                pr.x = pack_bf16x2(v.x, v.y);
                pr.y = pack_bf16x2(v.z, v.w);
                uint32_t o = drow + ((((uint32_t)(f >> 1)) ^ dxor) << 4)
                           + (uint32_t)(f & 1) * 8u;
                *reinterpret_cast<uint2*>(bb + o) = pr;
            }
            MBARRIER_ARRIVE(s ? fullb1 : fullb0);   // release: stores visible
            NAMED_BAR(2, 64);                        // staging[s] fully read
            if (tid == 256 && t + 2 < NT) {
                const int t2 = t + 2;
                const int row2 = rg + GROUPS * (t2 >> 2);
                MBARRIER_EXPECT_TX(dmab, 32768);
                bulk_g2s(sb + STG_OFF + s * 32768,
                         keys + ((size_t)row2 * VPR + (size_t)(t2 & 3) * 64) * DIM,
                         32768, dmab);
            }
        }
    } else {
        // ================= consumer: MMA warps (256 threads) =================
        const int wy = wid >> 1;
        const int wn = wid & 1;
        const int mbase = wy * 32;
        const int nbase = wn * 32;

        const uint32_t aoff = (uint32_t)(mbase + (lane & 15)) * 256u;
        const uint32_t boff = (uint32_t)(nbase + ((lane & 7) | ((lane >> 4) << 3))) * 256u;
        const int axor = lane & 7;
        const int acq  = lane >> 4;
        const int bcq  = (lane >> 3) & 1;

        // hoist A fragments (Q resident)
        uint32_t aH[8][2][4];
        #pragma unroll
        for (int kp = 0; kp < 8; ++kp) {
            const uint32_t aswz = (uint32_t)(((kp * 2 + acq) ^ axor) << 4);
            #pragma unroll
            for (int mt = 0; mt < 2; ++mt)
                LDSM_X4(aH[kp][mt][0], aH[kp][mt][1], aH[kp][mt][2], aH[kp][mt][3],
                        sb + aoff + (uint32_t)mt * 4096u + aswz);
        }

        float run_v[4];

        for (int tt = 0; tt < NT; ++tt) {
            const int u = tt >> 1, s = tt & 1;
            const int row = rg + GROUPS * (tt >> 2);
            const int qtr = tt & 3;

            MBARRIER_WAIT_PARITY(s ? fullb1 : fullb0, u & 1);

            float acc[2][4][4];
            #pragma unroll
            for (int mt = 0; mt < 2; ++mt)
                #pragma unroll
                for (int nt = 0; nt < 4; ++nt)
                    #pragma unroll
                    for (int r = 0; r < 4; ++r) acc[mt][nt][r] = 0.f;

            const uint32_t bbase = sb + BBUF_OFF + (uint32_t)s * 16384u;

            #pragma unroll
            for (int kp = 0; kp < 8; ++kp) {
                uint32_t b[4][2];
                const uint32_t bswz = (uint32_t)(((kp * 2 + bcq) ^ axor) << 4);
                #pragma unroll
                for (int h = 0; h < 2; ++h) {
                    uint32_t r0, r1, r2, r3;
                    LDSM_X4(r0, r1, r2, r3, bbase + boff + (uint32_t)h * 4096u + bswz);
                    b[2*h  ][0] = r0; b[2*h  ][1] = r1;
                    b[2*h+1][0] = r2; b[2*h+1][1] = r3;
                }
                #pragma unroll
                for (int mt = 0; mt < 2; ++mt)
                    #pragma unroll
                    for (int nt = 0; nt < 4; ++nt)
                        MMA16816(acc[mt][nt], aH[kp][mt], b[nt]);
            }
            MBARRIER_ARRIVE(s ? emptb1 : emptb0);

            // epilogue: running max over this tile's 64 keys
            #pragma unroll
            for (int mt = 0; mt < 2; ++mt) {
                #pragma unroll
                for (int rh = 0; rh < 2; ++rh) {
                    const int sl = mt * 2 + rh;
                    float v = -3.4e38f;
                    #pragma unroll
                    for (int nt = 0; nt < 4; ++nt) {
                        v = fmaxf(v, acc[mt][nt][rh * 2 + 0]);
                        v = fmaxf(v, acc[mt][nt][rh * 2 + 1]);
                    }
                    v = fmaxf(v, __shfl_xor_sync(0xffffffffu, v, 1));
                    v = fmaxf(v, __shfl_xor_sync(0xffffffffu, v, 2));
                    if (qtr == 0) run_v[sl] = v;
                    else          run_v[sl] = fmaxf(run_v[sl], v);
                }
            }

            if (qtr == 3) {
                if ((lane & 3) == 0) {
                    #pragma unroll
                    for (int mt = 0; mt < 2; ++mt)
                        #pragma unroll
                        for (int rh = 0; rh < 2; ++rh) {
                            int r = mbase + mt * 16 + rh * 8 + (lane >> 2);
                            xv[wn][r] = run_v[mt * 2 + rh];
                        }
                }
                NAMED_BAR(1, 256);
                if (tid < 128)
                    g_rowmax[(size_t)(q0 + tid) * NROWS + row] =
                        fmaxf(xv[0][tid], xv[1][tid]);
                NAMED_BAR(1, 256);
            }
        }
    }
}

// ---------------------------------------------------------------------------
// Pass A2: threshold select — superset of top-64 rows per query.
// ---------------------------------------------------------------------------
__global__ void __launch_bounds__(256)
topsel_kernel()
{
    extern __shared__ uint32_t hist[];          // 8192 bins
    __shared__ int csum[256];
    __shared__ int s_binB;
    __shared__ int s_cc;

    const int q = blockIdx.x, tid = threadIdx.x;
    const float* src = g_rowmax + (size_t)q * NROWS;

    for (int i = tid; i < 8192; i += 256) hist[i] = 0;
    __syncthreads();

    for (int r = tid; r < NROWS; r += 256)
        atomicAdd(&hist[ford(src[r]) >> 19], 1u);
    __syncthreads();

    int local = 0;
    #pragma unroll
    for (int k = 0; k < 32; ++k) local += (int)hist[8191 - (32 * tid + k)];
    csum[tid] = local;
    __syncthreads();
    for (int off = 1; off < 256; off <<= 1) {
        int v = (tid >= off) ? csum[tid - off] : 0;
        __syncthreads();
        csum[tid] += v;
        __syncthreads();
    }
    int incl = csum[tid];
    int excl = incl - local;
    if (excl < 64 && incl >= 64) {
        int c = excl;
        for (int k = 0; k < 32; ++k) {
            c += (int)hist[8191 - (32 * tid + k)];
            if (c >= 64) { s_binB = 8191 - (32 * tid + k); break; }
        }
    }
    if (tid == 0) s_cc = 0;
    __syncthreads();

    const uint32_t binB = (uint32_t)s_binB;
    for (int r = tid; r < NROWS; r += 256) {
        if ((ford(src[r]) >> 19) >= binB) {
            int p = atomicAdd(&s_cc, 1);
            if (p < RCAP) g_cand[(size_t)q * RCAP + p] = r;
        }
    }
    __syncthreads();
    if (tid == 0) g_qcnt[q] = min(s_cc, RCAP);
}

// ---------------------------------------------------------------------------
__global__ void zero_kernel()
{
    int i = blockIdx.x * 256 + threadIdx.x;
    if (i < NROWS) g_rowcnt[i] = 0;
}

__global__ void __launch_bounds__(256)
scatter_kernel()
{
    const int q = blockIdx.x, slot = threadIdx.x;
    if (slot < g_qcnt[q]) {
        int row = g_cand[(size_t)q * RCAP + slot];
        int idx = atomicAdd(&g_rowcnt[row], 1);
        g_rowlist[(size_t)row * NQ + idx] = (q << 8) | slot;
    }
}

// ---------------------------------------------------------------------------
// Pass B: exact fp32 rescore; 2 CTAs per row, warp-per-entry (no CTA sync).
// ---------------------------------------------------------------------------
#define SMEM_R 65536

__global__ void __launch_bounds__(256)
rescore_kernel(const float* __restrict__ queries, const float* __restrict__ keys)
{
    const int row = blockIdx.x >> 1;
    const int h   = blockIdx.x & 1;
    const int cnt = g_rowcnt[row];
    if (cnt == 0) return;

    extern __shared__ __align__(1024) float Ks[];   // 128 keys x 128 dims fp32
    __shared__ unsigned long long s_mbar;

    const int tid  = threadIdx.x;
    const int lane = tid & 31;
    const int w    = tid >> 5;

    const uint32_t mbar = smem_u32(&s_mbar);
    if (tid == 0) MBARRIER_INIT(mbar, 1);
    __syncthreads();
    if (tid == 0) {
        MBARRIER_EXPECT_TX(mbar, 65536);
        bulk_g2s(smem_u32(Ks), keys + ((size_t)row * VPR + (size_t)h * 128) * DIM,
                 65536, mbar);
    }
    MBARRIER_WAIT_PARITY(mbar, 0);

    // warp w handles entries w, w+8, ... fully (dims across lanes)
    for (int i = w; i < cnt; i += 8) {
        const int e = g_rowlist[(size_t)row * NQ + i];
        const int q = e >> 8, slot = e & 255;

        float4 qv = *reinterpret_cast<const float4*>(queries + (size_t)q * DIM + lane * 4);

        unsigned long long best = 0ull;
        #pragma unroll 4
        for (int kl = 0; kl < 128; ++kl) {
            float4 kv = *reinterpret_cast<const float4*>(Ks + (size_t)kl * DIM + lane * 4);
            float d = qv.x * kv.x;
            d = fmaf(qv.y, kv.y, d);
            d = fmaf(qv.z, kv.z, d);
            d = fmaf(qv.w, kv.w, d);
            #pragma unroll
            for (int o = 16; o > 0; o >>= 1) d += __shfl_xor_sync(0xffffffffu, d, o);
            int gk = h * 128 + kl;
            unsigned long long p = ((unsigned long long)ford(d) << 32) | (uint32_t)(~gk);
            if (p > best) best = p;            // ascending gk -> tie keeps lowest
        }
        if (lane == 0) {
            size_t o = ((size_t)q * RCAP + slot) * 2 + h;
            g_exs2[o] = funord((uint32_t)(best >> 32));
            g_exa2[o] = (int)((uint8_t)(~(uint32_t)best));
        }
    }
}

// ---------------------------------------------------------------------------
// Pass C: merge halves, exact top-32, mask/softmax/gather outputs.
// ---------------------------------------------------------------------------
__device__ __forceinline__ void put(float* out, long long off, long long lim, float v) {
    if (off < lim) out[off] = v;
}

__global__ void __launch_bounds__(128)
finalize_kernel(const float* __restrict__ values, const int* __restrict__ mem_ids,
                const int* __restrict__ ent_ids, const int* __restrict__ text_ids,
                float* __restrict__ out, long long lim)
{
    volatile __shared__ float cs[RCAP];
    __shared__ int   cm[RCAP];
    __shared__ int   ca[RCAP];
    __shared__ int   ssel[KSEL];
    __shared__ float ssc[KSEL];
    __shared__ int   sid[KSEL];

    const int q = blockIdx.x, tid = threadIdx.x;
    const int cnt = g_qcnt[q];

    for (int s = tid; s < cnt; s += 128) {
        size_t o = ((size_t)q * RCAP + s) * 2;
        float s0 = g_exs2[o], s1 = g_exs2[o + 1];
        int   a0 = g_exa2[o], a1 = g_exa2[o + 1];
        float sc; int aa;
        if (s1 > s0) { sc = s1; aa = a1; } else { sc = s0; aa = a0; }
        cs[s] = sc;
        ca[s] = aa;
        cm[s] = (g_cand[(size_t)q * RCAP + s] << 8) | s;
    }
    __syncthreads();

    if (tid < 32) {
        for (int it = 0; it < KSEL; ++it) {
            float bv = -3.4e38f; int bm = 0x7FFFFFFF;
            #pragma unroll
            for (int k = 0; k < 8; ++k) {
                int s = tid + 32 * k;
                if (s < cnt) {
                    float v = cs[s]; int m = cm[s];
                    if (v > bv || (v == bv && m < bm)) { bv = v; bm = m; }
                }
            }
            #pragma unroll
            for (int o = 16; o > 0; o >>= 1) {
                float v2 = __shfl_xor_sync(0xffffffffu, bv, o);
                int   m2 = __shfl_xor_sync(0xffffffffu, bm, o);
                if (v2 > bv || (v2 == bv && m2 < bm)) { bv = v2; bm = m2; }
            }
            if (tid == 0) { ssel[it] = bm; ssc[it] = bv; cs[bm & 255] = -3.4e38f; }
            __syncwarp();
        }
    }
    __syncthreads();

    if (tid < KSEL) {
        int meta = ssel[tid];
        int slot = meta & 255, row = meta >> 8;
        float sc = ssc[tid];
        int   id = row * VPR + ca[slot];
        sid[tid] = id;

        int   m  = (mem_ids[id] == text_ids[q]) ? 1 : 0;
        float ms = sc - (float)m * 1e10f;

        float mx = ms;
        #pragma unroll
        for (int o = 16; o > 0; o >>= 1) mx = fmaxf(mx, __shfl_xor_sync(0xffffffffu, mx, o));
        float e = expf(ms - mx);
        float ssum = e;
        #pragma unroll
        for (int o = 16; o > 0; o >>= 1) ssum += __shfl_xor_sync(0xffffffffu, ssum, o);
        float wgt = e / ssum;

        int cdis = m;
        #pragma unroll
        for (int o = 16; o > 0; o >>= 1) cdis += __shfl_xor_sync(0xffffffffu, cdis, o);
        if (tid == 0) g_qdis[q] = cdis;

        long long base = (long long)q * KSEL + tid;
        put(out, OFF_ENT  + base, lim, (float)ent_ids[id]);
        put(out, OFF_GID  + base, lim, (float)id);
        put(out, OFF_SC   + base, lim, sc);
        put(out, OFF_MASK + base, lim, (float)m);
        put(out, OFF_ATTN + base, lim, wgt);
    }
    __syncthreads();

    for (int j = 0; j < KSEL; ++j) {
        int id = sid[j];
        long long o = OFF_VAL + ((long long)(q * KSEL + j)) * DIM + tid;
        if (o < lim) out[o] = values[(size_t)id * DIM + tid];
    }
}

// ---------------------------------------------------------------------------
__global__ void __launch_bounds__(512)
ndis_kernel(float* __restrict__ out, long long lim)
{
    __shared__ int s[512];
    int t = threadIdx.x;
    s[t] = g_qdis[t];
    __syncthreads();
    for (int st = 256; st > 0; st >>= 1) {
        if (t < st) s[t] += s[t + st];
        __syncthreads();
    }
    if (t == 0 && OFF_NDIS < lim) out[OFF_NDIS] = (float)s[0];
}

// ---------------------------------------------------------------------------
extern "C" void kernel_launch(void* const* d_in, const int* in_sizes, int n_in,
                              void* d_out, int out_size)
{
    const float* queries  = (const float*)d_in[0];
    const float* keys     = (const float*)d_in[1];
    const int*   mem_ids  = (const int*)d_in[2];
    const int*   ent_ids  = (const int*)d_in[3];
    const float* values   = (const float*)d_in[4];
    const int*   text_ids = (const int*)d_in[5];
    float* out = (float*)d_out;
    long long lim = (long long)out_size;

    cudaFuncSetAttribute(score_approx,   cudaFuncAttributeMaxDynamicSharedMemorySize, SMEM_A);
    cudaFuncSetAttribute(rescore_kernel, cudaFuncAttributeMaxDynamicSharedMemorySize, SMEM_R);
    cudaFuncSetAttribute(topsel_kernel,  cudaFuncAttributeMaxDynamicSharedMemorySize, 8192 * 4);

    score_approx<<<4 * GROUPS, 320, SMEM_A>>>(queries, keys);
    topsel_kernel<<<NQ, 256, 8192 * 4>>>();
    zero_kernel<<<(NROWS + 255) / 256, 256>>>();
    scatter_kernel<<<NQ, 256>>>();
    rescore_kernel<<<2 * NROWS, 256, SMEM_R>>>(queries, keys);
    finalize_kernel<<<NQ, 128>>>(values, mem_ids, ent_ids, text_ids, out, lim);
    ndis_kernel<<<1, 512>>>(out, lim);
}

// round 12
// speedup vs baseline: 1.2229x; 1.2229x over previous
#include <cuda_runtime.h>
#include <math.h>
#include <stdint.h>

// Problem constants
#define NQ     512
#define NROWS  4096
#define VPR    256
#define DIM    128
#define KSEL   32
#define RCAP   256

// Output layout (flat float32 concat, reference tuple order)
#define OFF_VAL   0LL
#define OFF_ENT   2097152LL
#define OFF_GID   2113536LL
#define OFF_SC    2129920LL
#define OFF_MASK  2146304LL
#define OFF_NDIS  2162688LL
#define OFF_ATTN  2162689LL

// ---------------------------------------------------------------------------
// helpers
// ---------------------------------------------------------------------------
__device__ __forceinline__ uint32_t smem_u32(const void* p) {
    uint32_t a;
    asm("{ .reg .u64 t; cvta.to.shared.u64 t, %1; cvt.u32.u64 %0, t; }" : "=r"(a) : "l"(p));
    return a;
}

#define LDSM_X4(r0, r1, r2, r3, addr) \
    asm volatile("ldmatrix.sync.aligned.m8n8.x4.shared.b16 {%0,%1,%2,%3}, [%4];" \
        : "=r"(r0), "=r"(r1), "=r"(r2), "=r"(r3) : "r"(addr))

#define MMA16816(d, a, b) \
    asm volatile("mma.sync.aligned.m16n8k16.row.col.f32.bf16.bf16.f32 " \
        "{%0,%1,%2,%3}, {%4,%5,%6,%7}, {%8,%9}, {%0,%1,%2,%3};" \
        : "+f"((d)[0]), "+f"((d)[1]), "+f"((d)[2]), "+f"((d)[3]) \
        : "r"((a)[0]), "r"((a)[1]), "r"((a)[2]), "r"((a)[3]), \
          "r"((b)[0]), "r"((b)[1]))

__device__ __forceinline__ uint32_t pack_bf16x2(float lo, float hi) {
    uint32_t r;
    asm("cvt.rn.bf16x2.f32 %0, %1, %2;" : "=r"(r) : "f"(hi), "f"(lo));
    return r;
}

__device__ __forceinline__ uint32_t ford(float s) {
    uint32_t u = __float_as_uint(s);
    return (u & 0x80000000u) ? ~u : (u | 0x80000000u);
}
__device__ __forceinline__ float funord(uint32_t u) {
    return (u & 0x80000000u) ? __uint_as_float(u & 0x7FFFFFFFu) : __uint_as_float(~u);
}

#define MBARRIER_INIT(mb, cnt) \
    asm volatile("mbarrier.init.shared.b64 [%0], %1;" :: "r"((uint32_t)(mb)), "r"((uint32_t)(cnt)) : "memory")
#define MBARRIER_EXPECT_TX(mb, bytes) \
    asm volatile("mbarrier.arrive.expect_tx.shared.b64 _, [%0], %1;" :: "r"((uint32_t)(mb)), "r"((uint32_t)(bytes)) : "memory")
#define MBARRIER_WAIT_PARITY(mb, par) do { \
    uint32_t _mb = (uint32_t)(mb); uint32_t _pa = (uint32_t)(par); uint32_t _dn; \
    asm volatile("{\n\t.reg .pred p;\n\tmbarrier.try_wait.parity.acquire.cta.shared::cta.b64 p, [%1], %2;\n\tselp.b32 %0, 1, 0, p;\n\t}" \
        : "=r"(_dn) : "r"(_mb), "r"(_pa) : "memory"); \
    if (!_dn) { \
        asm volatile("{\n\t.reg .pred P1;\n\tWL_%=:\n\tmbarrier.try_wait.parity.acquire.cta.shared::cta.b64 P1, [%0], %1, 0x989680;\n\t@P1 bra.uni WD_%=;\n\tbra.uni WL_%=;\n\tWD_%=:\n\t}" \
            :: "r"(_mb), "r"(_pa) : "memory"); \
    } \
} while (0)

__device__ __forceinline__ void bulk_g2s(uint32_t dst, const void* src, uint32_t bytes, uint32_t mbar) {
    asm volatile("cp.async.bulk.shared::cluster.global.mbarrier::complete_tx::bytes [%0], [%1], %2, [%3];"
        :: "r"(dst), "l"(src), "r"(bytes), "r"(mbar) : "memory");
}

// ---------------------------------------------------------------------------
// Scratch
// ---------------------------------------------------------------------------
__device__ float g_rowmax[(size_t)NQ*NROWS];
__device__ int   g_cand[(size_t)NQ*RCAP];
__device__ int   g_qcnt[NQ];
__device__ int   g_rowcnt[NROWS];
__device__ int   g_rowlist[(size_t)NROWS*NQ];
__device__ float g_exs2[(size_t)NQ*RCAP*2];
__device__ int   g_exa2[(size_t)NQ*RCAP*2];
__device__ int   g_qdis[NQ];

// ---------------------------------------------------------------------------
// Pass A: approximate scores (1-term bf16 HMMA), keys streamed by bulk DMA.
// CTA = 256 thr; tile M=128 q x N=64 keys x K=128; 2 CTAs/SM for overlap.
// All 8 kp A-fragments hoisted to registers: crossbar/tile = B 64KB + cvt 48KB
// = 112KB (<1024-cyc MMA floor) -> MMA-bound.
// smem: Q bf16 32KB | B bf16 2x16KB | fp32 staging 32KB   (98304 B dynamic)
// ---------------------------------------------------------------------------
#define GROUPS   74
#define BBUF_OFF 32768
#define STG_OFF  65536
#define SMEM_A   98304

__global__ void __launch_bounds__(256, 2)
score_approx(const float* __restrict__ queries, const float* __restrict__ keys)
{
    extern __shared__ __align__(1024) char sm[];
    const uint32_t sb = smem_u32(sm);
    __shared__ float xv[2][128];
    __shared__ unsigned long long s_mbar;

    const int tid  = threadIdx.x;
    const int wid  = tid >> 5;
    const int lane = tid & 31;
    const int qt   = blockIdx.x & 3;
    const int rg   = blockIdx.x >> 2;
    const int q0   = qt * 128;

    const int wy = wid >> 1;
    const int wn = wid & 1;
    const int mbase = wy * 32;
    const int nbase = wn * 32;

    const uint32_t mbar = smem_u32(&s_mbar);
    if (tid == 0) MBARRIER_INIT(mbar, 1);
    __syncthreads();

    const int nrows = (NROWS - rg + GROUPS - 1) / GROUPS;
    const int NT = nrows * 4;

    // issue DMA for tile 0 (overlaps Q prologue)
    if (tid == 0) {
        MBARRIER_EXPECT_TX(mbar, 32768);
        bulk_g2s(sb + STG_OFF, keys + (size_t)rg * VPR * DIM, 32768, mbar);
    }

    // ---- Q prologue: fp32 -> bf16 -> swizzled smem ----
    {
        int q = tid >> 1, h = tid & 1;
        const float4* qp = reinterpret_cast<const float4*>(
            queries + (size_t)(q0 + q) * DIM + h * 64);
        #pragma unroll
        for (int jj = 0; jj < 8; ++jj) {
            float4 x = qp[2*jj], y = qp[2*jj+1];
            uint4 s0;
            s0.x = pack_bf16x2(x.x, x.y);
            s0.y = pack_bf16x2(x.z, x.w);
            s0.z = pack_bf16x2(y.x, y.y);
            s0.w = pack_bf16x2(y.z, y.w);
            int cb = h * 8 + jj;
            uint32_t o = (uint32_t)q * 256u + (uint32_t)((cb ^ (q & 7)) << 4);
            *reinterpret_cast<uint4*>(sm + o) = s0;
        }
    }

    // convert mapping: key cvn = tid>>2 (0..63), 128B part cvp = tid&3
    const int cvn = tid >> 2;
    const int cvp = tid & 3;
    const int rot = tid & 7;
    const uint32_t stg4 = (uint32_t)cvn * 32u + (uint32_t)cvp * 8u;
    const uint32_t drow = (uint32_t)cvn * 256u;
    const uint32_t dxor = (uint32_t)(cvn & 7);

    // wait tile 0, convert into buf 0
    int bph = 0;
    MBARRIER_WAIT_PARITY(mbar, 0); bph = 1;
    {
        const float4* stg = reinterpret_cast<const float4*>(sm + STG_OFF);
        #pragma unroll
        for (int jj = 0; jj < 8; ++jj) {
            int m = jj ^ rot;
            int f = cvp * 8 + m;
            float4 v = stg[stg4 + m];
            uint2 s; s.x = pack_bf16x2(v.x, v.y); s.y = pack_bf16x2(v.z, v.w);
            uint32_t o = drow + (uint32_t)((((uint32_t)(f >> 1)) ^ dxor) << 4) + (uint32_t)(f & 1) * 8u;
            *reinterpret_cast<uint2*>(sm + BBUF_OFF + o) = s;
        }
    }
    __syncthreads();
    if (tid == 0 && NT > 1) {
        MBARRIER_EXPECT_TX(mbar, 32768);
        bulk_g2s(sb + STG_OFF, keys + ((size_t)rg * VPR + 64) * DIM, 32768, mbar);
    }

    // ldmatrix lane invariants
    const uint32_t aoff = (uint32_t)(mbase + (lane & 15)) * 256u;
    const uint32_t boff = (uint32_t)(nbase + ((lane & 7) | ((lane >> 4) << 3))) * 256u;
    const int axor = lane & 7;
    const int acq  = lane >> 4;
    const int bcq  = (lane >> 3) & 1;

    // hoist ALL A fragments (Q resident for the whole kernel): 64 regs
    uint32_t aH[8][2][4];
    #pragma unroll
    for (int kp = 0; kp < 8; ++kp) {
        const uint32_t aswz = (uint32_t)(((kp * 2 + acq) ^ axor) << 4);
        #pragma unroll
        for (int mt = 0; mt < 2; ++mt)
            LDSM_X4(aH[kp][mt][0], aH[kp][mt][1], aH[kp][mt][2], aH[kp][mt][3],
                    sb + aoff + (uint32_t)mt * 4096u + aswz);
    }

    float run_v[4];

    for (int tt = 0; tt < NT; ++tt) {
        const int row = rg + GROUPS * (tt >> 2);
        const int qtr = tt & 3;
        const int buf = tt & 1;

        // ---- compute on buf ----
        float acc[2][4][4];
        #pragma unroll
        for (int mt = 0; mt < 2; ++mt)
            #pragma unroll
            for (int nt = 0; nt < 4; ++nt)
                #pragma unroll
                for (int r = 0; r < 4; ++r) acc[mt][nt][r] = 0.f;

        const uint32_t bbase = sb + BBUF_OFF + (uint32_t)buf * 16384u;

        #pragma unroll
        for (int kp = 0; kp < 8; ++kp) {
            uint32_t b[4][2];
            const uint32_t bswz = (uint32_t)(((kp * 2 + bcq) ^ axor) << 4);
            #pragma unroll
            for (int h = 0; h < 2; ++h) {
                uint32_t r0, r1, r2, r3;
                LDSM_X4(r0, r1, r2, r3, bbase + boff + (uint32_t)h * 4096u + bswz);
                b[2*h  ][0] = r0; b[2*h  ][1] = r1;
                b[2*h+1][0] = r2; b[2*h+1][1] = r3;
            }
            #pragma unroll
            for (int mt = 0; mt < 2; ++mt)
                #pragma unroll
                for (int nt = 0; nt < 4; ++nt)
                    MMA16816(acc[mt][nt], aH[kp][mt], b[nt]);
        }

        // ---- pipeline: wait DMA(t+1), convert to other buf, issue DMA(t+2) ----
        if (tt + 1 < NT) {
            MBARRIER_WAIT_PARITY(mbar, bph); bph ^= 1;
            const float4* stg = reinterpret_cast<const float4*>(sm + STG_OFF);
            char* bb = sm + BBUF_OFF + ((buf ^ 1) * 16384);
            #pragma unroll
            for (int jj = 0; jj < 8; ++jj) {
                int m = jj ^ rot;
                int f = cvp * 8 + m;
                float4 v = stg[stg4 + m];
                uint2 s; s.x = pack_bf16x2(v.x, v.y); s.y = pack_bf16x2(v.z, v.w);
                uint32_t o = drow + (uint32_t)((((uint32_t)(f >> 1)) ^ dxor) << 4) + (uint32_t)(f & 1) * 8u;
                *reinterpret_cast<uint2*>(bb + o) = s;
            }
            __syncthreads();
            if (tid == 0 && tt + 2 < NT) {
                int t2 = tt + 2;
                int row2 = rg + GROUPS * (t2 >> 2);
                MBARRIER_EXPECT_TX(mbar, 32768);
                bulk_g2s(sb + STG_OFF, keys + ((size_t)row2 * VPR + (size_t)(t2 & 3) * 64) * DIM,
                         32768, mbar);
            }
        }

        // ---- epilogue: per-query running max over this tile's 64 keys ----
        #pragma unroll
        for (int mt = 0; mt < 2; ++mt) {
            #pragma unroll
            for (int rh = 0; rh < 2; ++rh) {
                const int sl = mt * 2 + rh;
                float v = -3.4e38f;
                #pragma unroll
                for (int nt = 0; nt < 4; ++nt) {
                    v = fmaxf(v, acc[mt][nt][rh * 2 + 0]);
                    v = fmaxf(v, acc[mt][nt][rh * 2 + 1]);
                }
                v = fmaxf(v, __shfl_xor_sync(0xffffffffu, v, 1));
                v = fmaxf(v, __shfl_xor_sync(0xffffffffu, v, 2));
                if (qtr == 0) run_v[sl] = v;
                else          run_v[sl] = fmaxf(run_v[sl], v);
            }
        }

        if (qtr == 3) {
            if ((lane & 3) == 0) {
                #pragma unroll
                for (int mt = 0; mt < 2; ++mt)
                    #pragma unroll
                    for (int rh = 0; rh < 2; ++rh) {
                        int r = mbase + mt * 16 + rh * 8 + (lane >> 2);
                        xv[wn][r] = run_v[mt * 2 + rh];
                    }
            }
            __syncthreads();
            if (tid < 128)
                g_rowmax[(size_t)(q0 + tid) * NROWS + row] = fmaxf(xv[0][tid], xv[1][tid]);
            __syncthreads();
        }
    }
}

// ---------------------------------------------------------------------------
// Pass A2: threshold select — superset of top-64 rows per query.
// ---------------------------------------------------------------------------
__global__ void __launch_bounds__(256)
topsel_kernel()
{
    extern __shared__ uint32_t hist[];          // 8192 bins
    __shared__ int csum[256];
    __shared__ int s_binB;
    __shared__ int s_cc;

    const int q = blockIdx.x, tid = threadIdx.x;
    const float* src = g_rowmax + (size_t)q * NROWS;

    for (int i = tid; i < 8192; i += 256) hist[i] = 0;
    __syncthreads();

    for (int r = tid; r < NROWS; r += 256)
        atomicAdd(&hist[ford(src[r]) >> 19], 1u);
    __syncthreads();

    int local = 0;
    #pragma unroll
    for (int k = 0; k < 32; ++k) local += (int)hist[8191 - (32 * tid + k)];
    csum[tid] = local;
    __syncthreads();
    for (int off = 1; off < 256; off <<= 1) {
        int v = (tid >= off) ? csum[tid - off] : 0;
        __syncthreads();
        csum[tid] += v;
        __syncthreads();
    }
    int incl = csum[tid];
    int excl = incl - local;
    if (excl < 64 && incl >= 64) {
        int c = excl;
        for (int k = 0; k < 32; ++k) {
            c += (int)hist[8191 - (32 * tid + k)];
            if (c >= 64) { s_binB = 8191 - (32 * tid + k); break; }
        }
    }
    if (tid == 0) s_cc = 0;
    __syncthreads();

    const uint32_t binB = (uint32_t)s_binB;
    for (int r = tid; r < NROWS; r += 256) {
        if ((ford(src[r]) >> 19) >= binB) {
            int p = atomicAdd(&s_cc, 1);
            if (p < RCAP) g_cand[(size_t)q * RCAP + p] = r;
        }
    }
    __syncthreads();
    if (tid == 0) g_qcnt[q] = min(s_cc, RCAP);
}

// ---------------------------------------------------------------------------
__global__ void zero_kernel()
{
    int i = blockIdx.x * 256 + threadIdx.x;
    if (i < NROWS) g_rowcnt[i] = 0;
}

__global__ void __launch_bounds__(256)
scatter_kernel()
{
    const int q = blockIdx.x, slot = threadIdx.x;
    if (slot < g_qcnt[q]) {
        int row = g_cand[(size_t)q * RCAP + slot];
        int idx = atomicAdd(&g_rowcnt[row], 1);
        g_rowlist[(size_t)row * NQ + idx] = (q << 8) | slot;
    }
}

// ---------------------------------------------------------------------------
// Pass B: exact fp32 rescore; 2 CTAs per row, warp-per-entry (no CTA sync).
// ---------------------------------------------------------------------------
#define SMEM_R 65536

__global__ void __launch_bounds__(256)
rescore_kernel(const float* __restrict__ queries, const float* __restrict__ keys)
{
    const int row = blockIdx.x >> 1;
    const int h   = blockIdx.x & 1;
    const int cnt = g_rowcnt[row];
    if (cnt == 0) return;

    extern __shared__ __align__(1024) float Ks[];   // 128 keys x 128 dims fp32
    __shared__ unsigned long long s_mbar;

    const int tid  = threadIdx.x;
    const int lane = tid & 31;
    const int w    = tid >> 5;

    const uint32_t mbar = smem_u32(&s_mbar);
    if (tid == 0) MBARRIER_INIT(mbar, 1);
    __syncthreads();
    if (tid == 0) {
        MBARRIER_EXPECT_TX(mbar, 65536);
        bulk_g2s(smem_u32(Ks), keys + ((size_t)row * VPR + (size_t)h * 128) * DIM,
                 65536, mbar);
    }
    MBARRIER_WAIT_PARITY(mbar, 0);

    // warp w handles entries w, w+8, ... fully (dims across lanes)
    for (int i = w; i < cnt; i += 8) {
        const int e = g_rowlist[(size_t)row * NQ + i];
        const int q = e >> 8, slot = e & 255;

        float4 qv = *reinterpret_cast<const float4*>(queries + (size_t)q * DIM + lane * 4);

        unsigned long long best = 0ull;
        #pragma unroll 4
        for (int kl = 0; kl < 128; ++kl) {
            float4 kv = *reinterpret_cast<const float4*>(Ks + (size_t)kl * DIM + lane * 4);
            float d = qv.x * kv.x;
            d = fmaf(qv.y, kv.y, d);
            d = fmaf(qv.z, kv.z, d);
            d = fmaf(qv.w, kv.w, d);
            #pragma unroll
            for (int o = 16; o > 0; o >>= 1) d += __shfl_xor_sync(0xffffffffu, d, o);
            int gk = h * 128 + kl;
            unsigned long long p = ((unsigned long long)ford(d) << 32) | (uint32_t)(~gk);
            if (p > best) best = p;            // ascending gk -> tie keeps lowest
        }
        if (lane == 0) {
            size_t o = ((size_t)q * RCAP + slot) * 2 + h;
            g_exs2[o] = funord((uint32_t)(best >> 32));
            g_exa2[o] = (int)((uint8_t)(~(uint32_t)best));
        }
    }
}

// ---------------------------------------------------------------------------
// Pass C: merge halves, exact top-32, mask/softmax/gather outputs.
// ---------------------------------------------------------------------------
__device__ __forceinline__ void put(float* out, long long off, long long lim, float v) {
    if (off < lim) out[off] = v;
}

__global__ void __launch_bounds__(128)
finalize_kernel(const float* __restrict__ values, const int* __restrict__ mem_ids,
                const int* __restrict__ ent_ids, const int* __restrict__ text_ids,
                float* __restrict__ out, long long lim)
{
    volatile __shared__ float cs[RCAP];
    __shared__ int   cm[RCAP];
    __shared__ int   ca[RCAP];
    __shared__ int   ssel[KSEL];
    __shared__ float ssc[KSEL];
    __shared__ int   sid[KSEL];

    const int q = blockIdx.x, tid = threadIdx.x;
    const int cnt = g_qcnt[q];

    for (int s = tid; s < cnt; s += 128) {
        size_t o = ((size_t)q * RCAP + s) * 2;
        float s0 = g_exs2[o], s1 = g_exs2[o + 1];
        int   a0 = g_exa2[o], a1 = g_exa2[o + 1];
        float sc; int aa;
        if (s1 > s0) { sc = s1; aa = a1; } else { sc = s0; aa = a0; }
        cs[s] = sc;
        ca[s] = aa;
        cm[s] = (g_cand[(size_t)q * RCAP + s] << 8) | s;
    }
    __syncthreads();

    if (tid < 32) {
        for (int it = 0; it < KSEL; ++it) {
            float bv = -3.4e38f; int bm = 0x7FFFFFFF;
            #pragma unroll
            for (int k = 0; k < 8; ++k) {
                int s = tid + 32 * k;
                if (s < cnt) {
                    float v = cs[s]; int m = cm[s];
                    if (v > bv || (v == bv && m < bm)) { bv = v; bm = m; }
                }
            }
            #pragma unroll
            for (int o = 16; o > 0; o >>= 1) {
                float v2 = __shfl_xor_sync(0xffffffffu, bv, o);
                int   m2 = __shfl_xor_sync(0xffffffffu, bm, o);
                if (v2 > bv || (v2 == bv && m2 < bm)) { bv = v2; bm = m2; }
            }
            if (tid == 0) { ssel[it] = bm; ssc[it] = bv; cs[bm & 255] = -3.4e38f; }
            __syncwarp();
        }
    }
    __syncthreads();

    if (tid < KSEL) {
        int meta = ssel[tid];
        int slot = meta & 255, row = meta >> 8;
        float sc = ssc[tid];
        int   id = row * VPR + ca[slot];
        sid[tid] = id;

        int   m  = (mem_ids[id] == text_ids[q]) ? 1 : 0;
        float ms = sc - (float)m * 1e10f;

        float mx = ms;
        #pragma unroll
        for (int o = 16; o > 0; o >>= 1) mx = fmaxf(mx, __shfl_xor_sync(0xffffffffu, mx, o));
        float e = expf(ms - mx);
        float ssum = e;
        #pragma unroll
        for (int o = 16; o > 0; o >>= 1) ssum += __shfl_xor_sync(0xffffffffu, ssum, o);
        float wgt = e / ssum;

        int cdis = m;
        #pragma unroll
        for (int o = 16; o > 0; o >>= 1) cdis += __shfl_xor_sync(0xffffffffu, cdis, o);
        if (tid == 0) g_qdis[q] = cdis;

        long long base = (long long)q * KSEL + tid;
        put(out, OFF_ENT  + base, lim, (float)ent_ids[id]);
        put(out, OFF_GID  + base, lim, (float)id);
        put(out, OFF_SC   + base, lim, sc);
        put(out, OFF_MASK + base, lim, (float)m);
        put(out, OFF_ATTN + base, lim, wgt);
    }
    __syncthreads();

    for (int j = 0; j < KSEL; ++j) {
        int id = sid[j];
        long long o = OFF_VAL + ((long long)(q * KSEL + j)) * DIM + tid;
        if (o < lim) out[o] = values[(size_t)id * DIM + tid];
    }
}

// ---------------------------------------------------------------------------
__global__ void __launch_bounds__(512)
ndis_kernel(float* __restrict__ out, long long lim)
{
    __shared__ int s[512];
    int t = threadIdx.x;
    s[t] = g_qdis[t];
    __syncthreads();
    for (int st = 256; st > 0; st >>= 1) {
        if (t < st) s[t] += s[t + st];
        __syncthreads();
    }
    if (t == 0 && OFF_NDIS < lim) out[OFF_NDIS] = (float)s[0];
}

// ---------------------------------------------------------------------------
extern "C" void kernel_launch(void* const* d_in, const int* in_sizes, int n_in,
                              void* d_out, int out_size)
{
    const float* queries  = (const float*)d_in[0];
    const float* keys     = (const float*)d_in[1];
    const int*   mem_ids  = (const int*)d_in[2];
    const int*   ent_ids  = (const int*)d_in[3];
    const float* values   = (const float*)d_in[4];
    const int*   text_ids = (const int*)d_in[5];
    float* out = (float*)d_out;
    long long lim = (long long)out_size;

    cudaFuncSetAttribute(score_approx,   cudaFuncAttributeMaxDynamicSharedMemorySize, SMEM_A);
    cudaFuncSetAttribute(rescore_kernel, cudaFuncAttributeMaxDynamicSharedMemorySize, SMEM_R);
    cudaFuncSetAttribute(topsel_kernel,  cudaFuncAttributeMaxDynamicSharedMemorySize, 8192 * 4);

    score_approx<<<4 * GROUPS, 256, SMEM_A>>>(queries, keys);
    topsel_kernel<<<NQ, 256, 8192 * 4>>>();
    zero_kernel<<<(NROWS + 255) / 256, 256>>>();
    scatter_kernel<<<NQ, 256>>>();
    rescore_kernel<<<2 * NROWS, 256, SMEM_R>>>(queries, keys);
    finalize_kernel<<<NQ, 128>>>(values, mem_ids, ent_ids, text_ids, out, lim);
    ndis_kernel<<<1, 512>>>(out, lim);
}

// round 13
// speedup vs baseline: 1.2237x; 1.0007x over previous
#include <cuda_runtime.h>
#include <math.h>
#include <stdint.h>

// Problem constants
#define NQ     512
#define NROWS  4096
#define VPR    256
#define DIM    128
#define KSEL   32
#define RCAP   256

// Output layout (flat float32 concat, reference tuple order)
#define OFF_VAL   0LL
#define OFF_ENT   2097152LL
#define OFF_GID   2113536LL
#define OFF_SC    2129920LL
#define OFF_MASK  2146304LL
#define OFF_NDIS  2162688LL
#define OFF_ATTN  2162689LL

// ---------------------------------------------------------------------------
// helpers
// ---------------------------------------------------------------------------
__device__ __forceinline__ uint32_t smem_u32(const void* p) {
    uint32_t a;
    asm("{ .reg .u64 t; cvta.to.shared.u64 t, %1; cvt.u32.u64 %0, t; }" : "=r"(a) : "l"(p));
    return a;
}

#define LDSM_X4(r0, r1, r2, r3, addr) \
    asm volatile("ldmatrix.sync.aligned.m8n8.x4.shared.b16 {%0,%1,%2,%3}, [%4];" \
        : "=r"(r0), "=r"(r1), "=r"(r2), "=r"(r3) : "r"(addr))

#define MMA16816(d, a, b) \
    asm volatile("mma.sync.aligned.m16n8k16.row.col.f32.bf16.bf16.f32 " \
        "{%0,%1,%2,%3}, {%4,%5,%6,%7}, {%8,%9}, {%0,%1,%2,%3};" \
        : "+f"((d)[0]), "+f"((d)[1]), "+f"((d)[2]), "+f"((d)[3]) \
        : "r"((a)[0]), "r"((a)[1]), "r"((a)[2]), "r"((a)[3]), \
          "r"((b)[0]), "r"((b)[1]))

__device__ __forceinline__ uint32_t pack_bf16x2(float lo, float hi) {
    uint32_t r;
    asm("cvt.rn.bf16x2.f32 %0, %1, %2;" : "=r"(r) : "f"(hi), "f"(lo));
    return r;
}

__device__ __forceinline__ uint32_t ford(float s) {
    uint32_t u = __float_as_uint(s);
    return (u & 0x80000000u) ? ~u : (u | 0x80000000u);
}
__device__ __forceinline__ float funord(uint32_t u) {
    return (u & 0x80000000u) ? __uint_as_float(u & 0x7FFFFFFFu) : __uint_as_float(~u);
}

#define MBARRIER_INIT(mb, cnt) \
    asm volatile("mbarrier.init.shared.b64 [%0], %1;" :: "r"((uint32_t)(mb)), "r"((uint32_t)(cnt)) : "memory")
#define MBARRIER_EXPECT_TX(mb, bytes) \
    asm volatile("mbarrier.arrive.expect_tx.shared.b64 _, [%0], %1;" :: "r"((uint32_t)(mb)), "r"((uint32_t)(bytes)) : "memory")
#define MBARRIER_WAIT_PARITY(mb, par) do { \
    uint32_t _mb = (uint32_t)(mb); uint32_t _pa = (uint32_t)(par); uint32_t _dn; \
    asm volatile("{\n\t.reg .pred p;\n\tmbarrier.try_wait.parity.acquire.cta.shared::cta.b64 p, [%1], %2;\n\tselp.b32 %0, 1, 0, p;\n\t}" \
        : "=r"(_dn) : "r"(_mb), "r"(_pa) : "memory"); \
    if (!_dn) { \
        asm volatile("{\n\t.reg .pred P1;\n\tWL_%=:\n\tmbarrier.try_wait.parity.acquire.cta.shared::cta.b64 P1, [%0], %1, 0x989680;\n\t@P1 bra.uni WD_%=;\n\tbra.uni WL_%=;\n\tWD_%=:\n\t}" \
            :: "r"(_mb), "r"(_pa) : "memory"); \
    } \
} while (0)

__device__ __forceinline__ void bulk_g2s(uint32_t dst, const void* src, uint32_t bytes, uint32_t mbar) {
    asm volatile("cp.async.bulk.shared::cluster.global.mbarrier::complete_tx::bytes [%0], [%1], %2, [%3];"
        :: "r"(dst), "l"(src), "r"(bytes), "r"(mbar) : "memory");
}

// ---------------------------------------------------------------------------
// Scratch
// ---------------------------------------------------------------------------
__device__ float g_rowmax[(size_t)NQ*NROWS];
__device__ int   g_cand[(size_t)NQ*RCAP];
__device__ int   g_qcnt[NQ];
__device__ int   g_rowcnt[NROWS];
__device__ int   g_rowlist[(size_t)NROWS*NQ];
__device__ float g_exs2[(size_t)NQ*RCAP*2];
__device__ int   g_exa2[(size_t)NQ*RCAP*2];
__device__ int   g_qdis[NQ];

// ---------------------------------------------------------------------------
// Pass A: approximate scores (1-term bf16 HMMA), keys streamed by bulk DMA.
// CTA = 256 thr; tile M=128 q x N=64 keys x K=128; 2 CTAs/SM for overlap.
// All 8 kp A-fragments hoisted to registers: crossbar/tile = B 64KB + cvt 48KB
// = 112KB (<1024-cyc MMA floor) -> MMA-bound.
// smem: Q bf16 32KB | B bf16 2x16KB | fp32 staging 32KB   (98304 B dynamic)
// ---------------------------------------------------------------------------
#define GROUPS   74
#define BBUF_OFF 32768
#define STG_OFF  65536
#define SMEM_A   98304

__global__ void __launch_bounds__(256, 2)
score_approx(const float* __restrict__ queries, const float* __restrict__ keys)
{
    extern __shared__ __align__(1024) char sm[];
    const uint32_t sb = smem_u32(sm);
    __shared__ float xv[2][128];
    __shared__ unsigned long long s_mbar;

    const int tid  = threadIdx.x;
    const int wid  = tid >> 5;
    const int lane = tid & 31;
    const int qt   = blockIdx.x & 3;
    const int rg   = blockIdx.x >> 2;
    const int q0   = qt * 128;

    const int wy = wid >> 1;
    const int wn = wid & 1;
    const int mbase = wy * 32;
    const int nbase = wn * 32;

    const uint32_t mbar = smem_u32(&s_mbar);
    if (tid == 0) MBARRIER_INIT(mbar, 1);
    __syncthreads();

    const int nrows = (NROWS - rg + GROUPS - 1) / GROUPS;
    const int NT = nrows * 4;

    // issue DMA for tile 0 (overlaps Q prologue)
    if (tid == 0) {
        MBARRIER_EXPECT_TX(mbar, 32768);
        bulk_g2s(sb + STG_OFF, keys + (size_t)rg * VPR * DIM, 32768, mbar);
    }

    // ---- Q prologue: fp32 -> bf16 -> swizzled smem ----
    {
        int q = tid >> 1, h = tid & 1;
        const float4* qp = reinterpret_cast<const float4*>(
            queries + (size_t)(q0 + q) * DIM + h * 64);
        #pragma unroll
        for (int jj = 0; jj < 8; ++jj) {
            float4 x = qp[2*jj], y = qp[2*jj+1];
            uint4 s0;
            s0.x = pack_bf16x2(x.x, x.y);
            s0.y = pack_bf16x2(x.z, x.w);
            s0.z = pack_bf16x2(y.x, y.y);
            s0.w = pack_bf16x2(y.z, y.w);
            int cb = h * 8 + jj;
            uint32_t o = (uint32_t)q * 256u + (uint32_t)((cb ^ (q & 7)) << 4);
            *reinterpret_cast<uint4*>(sm + o) = s0;
        }
    }

    // convert mapping: key cvn = tid>>2 (0..63), 128B part cvp = tid&3
    const int cvn = tid >> 2;
    const int cvp = tid & 3;
    const int rot = tid & 7;
    const uint32_t stg4 = (uint32_t)cvn * 32u + (uint32_t)cvp * 8u;
    const uint32_t drow = (uint32_t)cvn * 256u;
    const uint32_t dxor = (uint32_t)(cvn & 7);

    // wait tile 0, convert into buf 0
    int bph = 0;
    MBARRIER_WAIT_PARITY(mbar, 0); bph = 1;
    {
        const float4* stg = reinterpret_cast<const float4*>(sm + STG_OFF);
        #pragma unroll
        for (int jj = 0; jj < 8; ++jj) {
            int m = jj ^ rot;
            int f = cvp * 8 + m;
            float4 v = stg[stg4 + m];
            uint2 s; s.x = pack_bf16x2(v.x, v.y); s.y = pack_bf16x2(v.z, v.w);
            uint32_t o = drow + (uint32_t)((((uint32_t)(f >> 1)) ^ dxor) << 4) + (uint32_t)(f & 1) * 8u;
            *reinterpret_cast<uint2*>(sm + BBUF_OFF + o) = s;
        }
    }
    __syncthreads();
    if (tid == 0 && NT > 1) {
        MBARRIER_EXPECT_TX(mbar, 32768);
        bulk_g2s(sb + STG_OFF, keys + ((size_t)rg * VPR + 64) * DIM, 32768, mbar);
    }

    // ldmatrix lane invariants
    const uint32_t aoff = (uint32_t)(mbase + (lane & 15)) * 256u;
    const uint32_t boff = (uint32_t)(nbase + ((lane & 7) | ((lane >> 4) << 3))) * 256u;
    const int axor = lane & 7;
    const int acq  = lane >> 4;
    const int bcq  = (lane >> 3) & 1;

    // hoist ALL A fragments (Q resident for the whole kernel): 64 regs
    uint32_t aH[8][2][4];
    #pragma unroll
    for (int kp = 0; kp < 8; ++kp) {
        const uint32_t aswz = (uint32_t)(((kp * 2 + acq) ^ axor) << 4);
        #pragma unroll
        for (int mt = 0; mt < 2; ++mt)
            LDSM_X4(aH[kp][mt][0], aH[kp][mt][1], aH[kp][mt][2], aH[kp][mt][3],
                    sb + aoff + (uint32_t)mt * 4096u + aswz);
    }

    float run_v[4];

    for (int tt = 0; tt < NT; ++tt) {
        const int row = rg + GROUPS * (tt >> 2);
        const int qtr = tt & 3;
        const int buf = tt & 1;

        // ---- compute on buf ----
        float acc[2][4][4];
        #pragma unroll
        for (int mt = 0; mt < 2; ++mt)
            #pragma unroll
            for (int nt = 0; nt < 4; ++nt)
                #pragma unroll
                for (int r = 0; r < 4; ++r) acc[mt][nt][r] = 0.f;

        const uint32_t bbase = sb + BBUF_OFF + (uint32_t)buf * 16384u;

        #pragma unroll
        for (int kp = 0; kp < 8; ++kp) {
            uint32_t b[4][2];
            const uint32_t bswz = (uint32_t)(((kp * 2 + bcq) ^ axor) << 4);
            #pragma unroll
            for (int h = 0; h < 2; ++h) {
                uint32_t r0, r1, r2, r3;
                LDSM_X4(r0, r1, r2, r3, bbase + boff + (uint32_t)h * 4096u + bswz);
                b[2*h  ][0] = r0; b[2*h  ][1] = r1;
                b[2*h+1][0] = r2; b[2*h+1][1] = r3;
            }
            #pragma unroll
            for (int mt = 0; mt < 2; ++mt)
                #pragma unroll
                for (int nt = 0; nt < 4; ++nt)
                    MMA16816(acc[mt][nt], aH[kp][mt], b[nt]);
        }

        // ---- pipeline: wait DMA(t+1), convert to other buf, issue DMA(t+2) ----
        if (tt + 1 < NT) {
            MBARRIER_WAIT_PARITY(mbar, bph); bph ^= 1;
            const float4* stg = reinterpret_cast<const float4*>(sm + STG_OFF);
            char* bb = sm + BBUF_OFF + ((buf ^ 1) * 16384);
            #pragma unroll
            for (int jj = 0; jj < 8; ++jj) {
                int m = jj ^ rot;
                int f = cvp * 8 + m;
                float4 v = stg[stg4 + m];
                uint2 s; s.x = pack_bf16x2(v.x, v.y); s.y = pack_bf16x2(v.z, v.w);
                uint32_t o = drow + (uint32_t)((((uint32_t)(f >> 1)) ^ dxor) << 4) + (uint32_t)(f & 1) * 8u;
                *reinterpret_cast<uint2*>(bb + o) = s;
            }
            __syncthreads();
            if (tid == 0 && tt + 2 < NT) {
                int t2 = tt + 2;
                int row2 = rg + GROUPS * (t2 >> 2);
                MBARRIER_EXPECT_TX(mbar, 32768);
                bulk_g2s(sb + STG_OFF, keys + ((size_t)row2 * VPR + (size_t)(t2 & 3) * 64) * DIM,
                         32768, mbar);
            }
        }

        // ---- epilogue: per-query running max over this tile's 64 keys ----
        #pragma unroll
        for (int mt = 0; mt < 2; ++mt) {
            #pragma unroll
            for (int rh = 0; rh < 2; ++rh) {
                const int sl = mt * 2 + rh;
                float v = -3.4e38f;
                #pragma unroll
                for (int nt = 0; nt < 4; ++nt) {
                    v = fmaxf(v, acc[mt][nt][rh * 2 + 0]);
                    v = fmaxf(v, acc[mt][nt][rh * 2 + 1]);
                }
                v = fmaxf(v, __shfl_xor_sync(0xffffffffu, v, 1));
                v = fmaxf(v, __shfl_xor_sync(0xffffffffu, v, 2));
                if (qtr == 0) run_v[sl] = v;
                else          run_v[sl] = fmaxf(run_v[sl], v);
            }
        }

        if (qtr == 3) {
            if ((lane & 3) == 0) {
                #pragma unroll
                for (int mt = 0; mt < 2; ++mt)
                    #pragma unroll
                    for (int rh = 0; rh < 2; ++rh) {
                        int r = mbase + mt * 16 + rh * 8 + (lane >> 2);
                        xv[wn][r] = run_v[mt * 2 + rh];
                    }
            }
            __syncthreads();
            if (tid < 128)
                g_rowmax[(size_t)(q0 + tid) * NROWS + row] = fmaxf(xv[0][tid], xv[1][tid]);
            __syncthreads();
        }
    }
}

// ---------------------------------------------------------------------------
// Pass A2: threshold select — superset of top-64 rows per query.
// ---------------------------------------------------------------------------
__global__ void __launch_bounds__(256)
topsel_kernel()
{
    extern __shared__ uint32_t hist[];          // 8192 bins
    __shared__ int csum[256];
    __shared__ int s_binB;
    __shared__ int s_cc;

    const int q = blockIdx.x, tid = threadIdx.x;
    const float* src = g_rowmax + (size_t)q * NROWS;

    for (int i = tid; i < 8192; i += 256) hist[i] = 0;
    __syncthreads();

    for (int r = tid; r < NROWS; r += 256)
        atomicAdd(&hist[ford(src[r]) >> 19], 1u);
    __syncthreads();

    int local = 0;
    #pragma unroll
    for (int k = 0; k < 32; ++k) local += (int)hist[8191 - (32 * tid + k)];
    csum[tid] = local;
    __syncthreads();
    for (int off = 1; off < 256; off <<= 1) {
        int v = (tid >= off) ? csum[tid - off] : 0;
        __syncthreads();
        csum[tid] += v;
        __syncthreads();
    }
    int incl = csum[tid];
    int excl = incl - local;
    if (excl < 64 && incl >= 64) {
        int c = excl;
        for (int k = 0; k < 32; ++k) {
            c += (int)hist[8191 - (32 * tid + k)];
            if (c >= 64) { s_binB = 8191 - (32 * tid + k); break; }
        }
    }
    if (tid == 0) s_cc = 0;
    __syncthreads();

    const uint32_t binB = (uint32_t)s_binB;
    for (int r = tid; r < NROWS; r += 256) {
        if ((ford(src[r]) >> 19) >= binB) {
            int p = atomicAdd(&s_cc, 1);
            if (p < RCAP) g_cand[(size_t)q * RCAP + p] = r;
        }
    }
    __syncthreads();
    if (tid == 0) g_qcnt[q] = min(s_cc, RCAP);
}

// ---------------------------------------------------------------------------
__global__ void zero_kernel()
{
    int i = blockIdx.x * 256 + threadIdx.x;
    if (i < NROWS) g_rowcnt[i] = 0;
}

__global__ void __launch_bounds__(256)
scatter_kernel()
{
    const int q = blockIdx.x, slot = threadIdx.x;
    if (slot < g_qcnt[q]) {
        int row = g_cand[(size_t)q * RCAP + slot];
        int idx = atomicAdd(&g_rowcnt[row], 1);
        g_rowlist[(size_t)row * NQ + idx] = (q << 8) | slot;
    }
}

// ---------------------------------------------------------------------------
// Pass B: exact fp32 rescore; 2 CTAs per row, warp-per-entry (no CTA sync).
// ---------------------------------------------------------------------------
#define SMEM_R 65536

__global__ void __launch_bounds__(256)
rescore_kernel(const float* __restrict__ queries, const float* __restrict__ keys)
{
    const int row = blockIdx.x >> 1;
    const int h   = blockIdx.x & 1;
    const int cnt = g_rowcnt[row];
    if (cnt == 0) return;

    extern __shared__ __align__(1024) float Ks[];   // 128 keys x 128 dims fp32
    __shared__ unsigned long long s_mbar;

    const int tid  = threadIdx.x;
    const int lane = tid & 31;
    const int w    = tid >> 5;

    const uint32_t mbar = smem_u32(&s_mbar);
    if (tid == 0) MBARRIER_INIT(mbar, 1);
    __syncthreads();
    if (tid == 0) {
        MBARRIER_EXPECT_TX(mbar, 65536);
        bulk_g2s(smem_u32(Ks), keys + ((size_t)row * VPR + (size_t)h * 128) * DIM,
                 65536, mbar);
    }
    MBARRIER_WAIT_PARITY(mbar, 0);

    // warp w handles entries w, w+8, ... fully (dims across lanes)
    for (int i = w; i < cnt; i += 8) {
        const int e = g_rowlist[(size_t)row * NQ + i];
        const int q = e >> 8, slot = e & 255;

        float4 qv = *reinterpret_cast<const float4*>(queries + (size_t)q * DIM + lane * 4);

        unsigned long long best = 0ull;
        #pragma unroll 4
        for (int kl = 0; kl < 128; ++kl) {
            float4 kv = *reinterpret_cast<const float4*>(Ks + (size_t)kl * DIM + lane * 4);
            float d = qv.x * kv.x;
            d = fmaf(qv.y, kv.y, d);
            d = fmaf(qv.z, kv.z, d);
            d = fmaf(qv.w, kv.w, d);
            #pragma unroll
            for (int o = 16; o > 0; o >>= 1) d += __shfl_xor_sync(0xffffffffu, d, o);
            int gk = h * 128 + kl;
            unsigned long long p = ((unsigned long long)ford(d) << 32) | (uint32_t)(~gk);
            if (p > best) best = p;            // ascending gk -> tie keeps lowest
        }
        if (lane == 0) {
            size_t o = ((size_t)q * RCAP + slot) * 2 + h;
            g_exs2[o] = funord((uint32_t)(best >> 32));
            g_exa2[o] = (int)((uint8_t)(~(uint32_t)best));
        }
    }
}

// ---------------------------------------------------------------------------
// Pass C: merge halves, exact top-32, mask/softmax/gather outputs.
// ---------------------------------------------------------------------------
__device__ __forceinline__ void put(float* out, long long off, long long lim, float v) {
    if (off < lim) out[off] = v;
}

__global__ void __launch_bounds__(128)
finalize_kernel(const float* __restrict__ values, const int* __restrict__ mem_ids,
                const int* __restrict__ ent_ids, const int* __restrict__ text_ids,
                float* __restrict__ out, long long lim)
{
    volatile __shared__ float cs[RCAP];
    __shared__ int   cm[RCAP];
    __shared__ int   ca[RCAP];
    __shared__ int   ssel[KSEL];
    __shared__ float ssc[KSEL];
    __shared__ int   sid[KSEL];

    const int q = blockIdx.x, tid = threadIdx.x;
    const int cnt = g_qcnt[q];

    for (int s = tid; s < cnt; s += 128) {
        size_t o = ((size_t)q * RCAP + s) * 2;
        float s0 = g_exs2[o], s1 = g_exs2[o + 1];
        int   a0 = g_exa2[o], a1 = g_exa2[o + 1];
        float sc; int aa;
        if (s1 > s0) { sc = s1; aa = a1; } else { sc = s0; aa = a0; }
        cs[s] = sc;
        ca[s] = aa;
        cm[s] = (g_cand[(size_t)q * RCAP + s] << 8) | s;
    }
    __syncthreads();

    if (tid < 32) {
        for (int it = 0; it < KSEL; ++it) {
            float bv = -3.4e38f; int bm = 0x7FFFFFFF;
            #pragma unroll
            for (int k = 0; k < 8; ++k) {
                int s = tid + 32 * k;
                if (s < cnt) {
                    float v = cs[s]; int m = cm[s];
                    if (v > bv || (v == bv && m < bm)) { bv = v; bm = m; }
                }
            }
            #pragma unroll
            for (int o = 16; o > 0; o >>= 1) {
                float v2 = __shfl_xor_sync(0xffffffffu, bv, o);
                int   m2 = __shfl_xor_sync(0xffffffffu, bm, o);
                if (v2 > bv || (v2 == bv && m2 < bm)) { bv = v2; bm = m2; }
            }
            if (tid == 0) { ssel[it] = bm; ssc[it] = bv; cs[bm & 255] = -3.4e38f; }
            __syncwarp();
        }
    }
    __syncthreads();

    if (tid < KSEL) {
        int meta = ssel[tid];
        int slot = meta & 255, row = meta >> 8;
        float sc = ssc[tid];
        int   id = row * VPR + ca[slot];
        sid[tid] = id;

        int   m  = (mem_ids[id] == text_ids[q]) ? 1 : 0;
        float ms = sc - (float)m * 1e10f;

        float mx = ms;
        #pragma unroll
        for (int o = 16; o > 0; o >>= 1) mx = fmaxf(mx, __shfl_xor_sync(0xffffffffu, mx, o));
        float e = expf(ms - mx);
        float ssum = e;
        #pragma unroll
        for (int o = 16; o > 0; o >>= 1) ssum += __shfl_xor_sync(0xffffffffu, ssum, o);
        float wgt = e / ssum;

        int cdis = m;
        #pragma unroll
        for (int o = 16; o > 0; o >>= 1) cdis += __shfl_xor_sync(0xffffffffu, cdis, o);
        if (tid == 0) g_qdis[q] = cdis;

        long long base = (long long)q * KSEL + tid;
        put(out, OFF_ENT  + base, lim, (float)ent_ids[id]);
        put(out, OFF_GID  + base, lim, (float)id);
        put(out, OFF_SC   + base, lim, sc);
        put(out, OFF_MASK + base, lim, (float)m);
        put(out, OFF_ATTN + base, lim, wgt);
    }
    __syncthreads();

    for (int j = 0; j < KSEL; ++j) {
        int id = sid[j];
        long long o = OFF_VAL + ((long long)(q * KSEL + j)) * DIM + tid;
        if (o < lim) out[o] = values[(size_t)id * DIM + tid];
    }
}

// ---------------------------------------------------------------------------
__global__ void __launch_bounds__(512)
ndis_kernel(float* __restrict__ out, long long lim)
{
    __shared__ int s[512];
    int t = threadIdx.x;
    s[t] = g_qdis[t];
    __syncthreads();
    for (int st = 256; st > 0; st >>= 1) {
        if (t < st) s[t] += s[t + st];
        __syncthreads();
    }
    if (t == 0 && OFF_NDIS < lim) out[OFF_NDIS] = (float)s[0];
}

// ---------------------------------------------------------------------------
extern "C" void kernel_launch(void* const* d_in, const int* in_sizes, int n_in,
                              void* d_out, int out_size)
{
    const float* queries  = (const float*)d_in[0];
    const float* keys     = (const float*)d_in[1];
    const int*   mem_ids  = (const int*)d_in[2];
    const int*   ent_ids  = (const int*)d_in[3];
    const float* values   = (const float*)d_in[4];
    const int*   text_ids = (const int*)d_in[5];
    float* out = (float*)d_out;
    long long lim = (long long)out_size;

    cudaFuncSetAttribute(score_approx,   cudaFuncAttributeMaxDynamicSharedMemorySize, SMEM_A);
    cudaFuncSetAttribute(rescore_kernel, cudaFuncAttributeMaxDynamicSharedMemorySize, SMEM_R);
    cudaFuncSetAttribute(topsel_kernel,  cudaFuncAttributeMaxDynamicSharedMemorySize, 8192 * 4);

    score_approx<<<4 * GROUPS, 256, SMEM_A>>>(queries, keys);
    topsel_kernel<<<NQ, 256, 8192 * 4>>>();
    zero_kernel<<<(NROWS + 255) / 256, 256>>>();
    scatter_kernel<<<NQ, 256>>>();
    rescore_kernel<<<2 * NROWS, 256, SMEM_R>>>(queries, keys);
    finalize_kernel<<<NQ, 128>>>(values, mem_ids, ent_ids, text_ids, out, lim);
    ndis_kernel<<<1, 512>>>(out, lim);
}

// round 14
// speedup vs baseline: 1.2239x; 1.0002x over previous
#include <cuda_runtime.h>
#include <math.h>
#include <stdint.h>

// Problem constants
#define NQ     512
#define NROWS  4096
#define VPR    256
#define DIM    128
#define KSEL   32
#define RCAP   256

// Output layout (flat float32 concat, reference tuple order)
#define OFF_VAL   0LL
#define OFF_ENT   2097152LL
#define OFF_GID   2113536LL
#define OFF_SC    2129920LL
#define OFF_MASK  2146304LL
#define OFF_NDIS  2162688LL
#define OFF_ATTN  2162689LL

// ---------------------------------------------------------------------------
// helpers
// ---------------------------------------------------------------------------
__device__ __forceinline__ uint32_t smem_u32(const void* p) {
    uint32_t a;
    asm("{ .reg .u64 t; cvta.to.shared.u64 t, %1; cvt.u32.u64 %0, t; }" : "=r"(a) : "l"(p));
    return a;
}

#define LDSM_X4(r0, r1, r2, r3, addr) \
    asm volatile("ldmatrix.sync.aligned.m8n8.x4.shared.b16 {%0,%1,%2,%3}, [%4];" \
        : "=r"(r0), "=r"(r1), "=r"(r2), "=r"(r3) : "r"(addr))

#define MMA16816(d, a, b) \
    asm volatile("mma.sync.aligned.m16n8k16.row.col.f32.bf16.bf16.f32 " \
        "{%0,%1,%2,%3}, {%4,%5,%6,%7}, {%8,%9}, {%0,%1,%2,%3};" \
        : "+f"((d)[0]), "+f"((d)[1]), "+f"((d)[2]), "+f"((d)[3]) \
        : "r"((a)[0]), "r"((a)[1]), "r"((a)[2]), "r"((a)[3]), \
          "r"((b)[0]), "r"((b)[1]))

__device__ __forceinline__ uint32_t pack_bf16x2(float lo, float hi) {
    uint32_t r;
    asm("cvt.rn.bf16x2.f32 %0, %1, %2;" : "=r"(r) : "f"(hi), "f"(lo));
    return r;
}

__device__ __forceinline__ uint32_t ford(float s) {
    uint32_t u = __float_as_uint(s);
    return (u & 0x80000000u) ? ~u : (u | 0x80000000u);
}
__device__ __forceinline__ float funord(uint32_t u) {
    return (u & 0x80000000u) ? __uint_as_float(u & 0x7FFFFFFFu) : __uint_as_float(~u);
}

#define MBARRIER_INIT(mb, cnt) \
    asm volatile("mbarrier.init.shared.b64 [%0], %1;" :: "r"((uint32_t)(mb)), "r"((uint32_t)(cnt)) : "memory")
#define MBARRIER_EXPECT_TX(mb, bytes) \
    asm volatile("mbarrier.arrive.expect_tx.shared.b64 _, [%0], %1;" :: "r"((uint32_t)(mb)), "r"((uint32_t)(bytes)) : "memory")
#define MBARRIER_WAIT_PARITY(mb, par) do { \
    uint32_t _mb = (uint32_t)(mb); uint32_t _pa = (uint32_t)(par); uint32_t _dn; \
    asm volatile("{\n\t.reg .pred p;\n\tmbarrier.try_wait.parity.acquire.cta.shared::cta.b64 p, [%1], %2;\n\tselp.b32 %0, 1, 0, p;\n\t}" \
        : "=r"(_dn) : "r"(_mb), "r"(_pa) : "memory"); \
    if (!_dn) { \
        asm volatile("{\n\t.reg .pred P1;\n\tWL_%=:\n\tmbarrier.try_wait.parity.acquire.cta.shared::cta.b64 P1, [%0], %1, 0x989680;\n\t@P1 bra.uni WD_%=;\n\tbra.uni WL_%=;\n\tWD_%=:\n\t}" \
            :: "r"(_mb), "r"(_pa) : "memory"); \
    } \
} while (0)

__device__ __forceinline__ void bulk_g2s(uint32_t dst, const void* src, uint32_t bytes, uint32_t mbar) {
    asm volatile("cp.async.bulk.shared::cluster.global.mbarrier::complete_tx::bytes [%0], [%1], %2, [%3];"
        :: "r"(dst), "l"(src), "r"(bytes), "r"(mbar) : "memory");
}

// ---------------------------------------------------------------------------
// Scratch
// ---------------------------------------------------------------------------
__device__ float g_rowmax[(size_t)NQ*NROWS];
__device__ int   g_cand[(size_t)NQ*RCAP];
__device__ int   g_qcnt[NQ];
__device__ int   g_rowcnt[NROWS];
__device__ int   g_rowlist[(size_t)NROWS*NQ];
__device__ float g_exs2[(size_t)NQ*RCAP*2];
__device__ int   g_exa2[(size_t)NQ*RCAP*2];
__device__ int   g_qdis[NQ];

// ---------------------------------------------------------------------------
// Pass A: approximate scores (1-term bf16 HMMA), keys streamed by bulk DMA.
// CTA = 256 thr; tile M=128 q x N=64 keys x K=128; 2 CTAs/SM for overlap.
// All 8 kp A-fragments hoisted to registers: crossbar/tile = B 64KB + cvt 48KB
// = 112KB (<1024-cyc MMA floor) -> MMA-bound.
// smem: Q bf16 32KB | B bf16 2x16KB | fp32 staging 32KB   (98304 B dynamic)
// ---------------------------------------------------------------------------
#define GROUPS   74
#define BBUF_OFF 32768
#define STG_OFF  65536
#define SMEM_A   98304

__global__ void __launch_bounds__(256, 2)
score_approx(const float* __restrict__ queries, const float* __restrict__ keys)
{
    extern __shared__ __align__(1024) char sm[];
    const uint32_t sb = smem_u32(sm);
    __shared__ float xv[2][128];
    __shared__ unsigned long long s_mbar;

    const int tid  = threadIdx.x;
    const int wid  = tid >> 5;
    const int lane = tid & 31;
    const int qt   = blockIdx.x & 3;
    const int rg   = blockIdx.x >> 2;
    const int q0   = qt * 128;

    const int wy = wid >> 1;
    const int wn = wid & 1;
    const int mbase = wy * 32;
    const int nbase = wn * 32;

    const uint32_t mbar = smem_u32(&s_mbar);
    if (tid == 0) MBARRIER_INIT(mbar, 1);
    __syncthreads();

    const int nrows = (NROWS - rg + GROUPS - 1) / GROUPS;
    const int NT = nrows * 4;

    // issue DMA for tile 0 (overlaps Q prologue)
    if (tid == 0) {
        MBARRIER_EXPECT_TX(mbar, 32768);
        bulk_g2s(sb + STG_OFF, keys + (size_t)rg * VPR * DIM, 32768, mbar);
    }

    // ---- Q prologue: fp32 -> bf16 -> swizzled smem ----
    {
        int q = tid >> 1, h = tid & 1;
        const float4* qp = reinterpret_cast<const float4*>(
            queries + (size_t)(q0 + q) * DIM + h * 64);
        #pragma unroll
        for (int jj = 0; jj < 8; ++jj) {
            float4 x = qp[2*jj], y = qp[2*jj+1];
            uint4 s0;
            s0.x = pack_bf16x2(x.x, x.y);
            s0.y = pack_bf16x2(x.z, x.w);
            s0.z = pack_bf16x2(y.x, y.y);
            s0.w = pack_bf16x2(y.z, y.w);
            int cb = h * 8 + jj;
            uint32_t o = (uint32_t)q * 256u + (uint32_t)((cb ^ (q & 7)) << 4);
            *reinterpret_cast<uint4*>(sm + o) = s0;
        }
    }

    // convert mapping: key cvn = tid>>2 (0..63), 128B part cvp = tid&3
    const int cvn = tid >> 2;
    const int cvp = tid & 3;
    const int rot = tid & 7;
    const uint32_t stg4 = (uint32_t)cvn * 32u + (uint32_t)cvp * 8u;
    const uint32_t drow = (uint32_t)cvn * 256u;
    const uint32_t dxor = (uint32_t)(cvn & 7);

    // wait tile 0, convert into buf 0
    int bph = 0;
    MBARRIER_WAIT_PARITY(mbar, 0); bph = 1;
    {
        const float4* stg = reinterpret_cast<const float4*>(sm + STG_OFF);
        #pragma unroll
        for (int jj = 0; jj < 8; ++jj) {
            int m = jj ^ rot;
            int f = cvp * 8 + m;
            float4 v = stg[stg4 + m];
            uint2 s; s.x = pack_bf16x2(v.x, v.y); s.y = pack_bf16x2(v.z, v.w);
            uint32_t o = drow + (uint32_t)((((uint32_t)(f >> 1)) ^ dxor) << 4) + (uint32_t)(f & 1) * 8u;
            *reinterpret_cast<uint2*>(sm + BBUF_OFF + o) = s;
        }
    }
    __syncthreads();
    if (tid == 0 && NT > 1) {
        MBARRIER_EXPECT_TX(mbar, 32768);
        bulk_g2s(sb + STG_OFF, keys + ((size_t)rg * VPR + 64) * DIM, 32768, mbar);
    }

    // ldmatrix lane invariants
    const uint32_t aoff = (uint32_t)(mbase + (lane & 15)) * 256u;
    const uint32_t boff = (uint32_t)(nbase + ((lane & 7) | ((lane >> 4) << 3))) * 256u;
    const int axor = lane & 7;
    const int acq  = lane >> 4;
    const int bcq  = (lane >> 3) & 1;

    // hoist ALL A fragments (Q resident for the whole kernel): 64 regs
    uint32_t aH[8][2][4];
    #pragma unroll
    for (int kp = 0; kp < 8; ++kp) {
        const uint32_t aswz = (uint32_t)(((kp * 2 + acq) ^ axor) << 4);
        #pragma unroll
        for (int mt = 0; mt < 2; ++mt)
            LDSM_X4(aH[kp][mt][0], aH[kp][mt][1], aH[kp][mt][2], aH[kp][mt][3],
                    sb + aoff + (uint32_t)mt * 4096u + aswz);
    }

    float run_v[4];

    for (int tt = 0; tt < NT; ++tt) {
        const int row = rg + GROUPS * (tt >> 2);
        const int qtr = tt & 3;
        const int buf = tt & 1;

        // ---- compute on buf ----
        float acc[2][4][4];
        #pragma unroll
        for (int mt = 0; mt < 2; ++mt)
            #pragma unroll
            for (int nt = 0; nt < 4; ++nt)
                #pragma unroll
                for (int r = 0; r < 4; ++r) acc[mt][nt][r] = 0.f;

        const uint32_t bbase = sb + BBUF_OFF + (uint32_t)buf * 16384u;

        #pragma unroll
        for (int kp = 0; kp < 8; ++kp) {
            uint32_t b[4][2];
            const uint32_t bswz = (uint32_t)(((kp * 2 + bcq) ^ axor) << 4);
            #pragma unroll
            for (int h = 0; h < 2; ++h) {
                uint32_t r0, r1, r2, r3;
                LDSM_X4(r0, r1, r2, r3, bbase + boff + (uint32_t)h * 4096u + bswz);
                b[2*h  ][0] = r0; b[2*h  ][1] = r1;
                b[2*h+1][0] = r2; b[2*h+1][1] = r3;
            }
            #pragma unroll
            for (int mt = 0; mt < 2; ++mt)
                #pragma unroll
                for (int nt = 0; nt < 4; ++nt)
                    MMA16816(acc[mt][nt], aH[kp][mt], b[nt]);
        }

        // ---- pipeline: wait DMA(t+1), convert to other buf, issue DMA(t+2) ----
        if (tt + 1 < NT) {
            MBARRIER_WAIT_PARITY(mbar, bph); bph ^= 1;
            const float4* stg = reinterpret_cast<const float4*>(sm + STG_OFF);
            char* bb = sm + BBUF_OFF + ((buf ^ 1) * 16384);
            #pragma unroll
            for (int jj = 0; jj < 8; ++jj) {
                int m = jj ^ rot;
                int f = cvp * 8 + m;
                float4 v = stg[stg4 + m];
                uint2 s; s.x = pack_bf16x2(v.x, v.y); s.y = pack_bf16x2(v.z, v.w);
                uint32_t o = drow + (uint32_t)((((uint32_t)(f >> 1)) ^ dxor) << 4) + (uint32_t)(f & 1) * 8u;
                *reinterpret_cast<uint2*>(bb + o) = s;
            }
            __syncthreads();
            if (tid == 0 && tt + 2 < NT) {
                int t2 = tt + 2;
                int row2 = rg + GROUPS * (t2 >> 2);
                MBARRIER_EXPECT_TX(mbar, 32768);
                bulk_g2s(sb + STG_OFF, keys + ((size_t)row2 * VPR + (size_t)(t2 & 3) * 64) * DIM,
                         32768, mbar);
            }
        }

        // ---- epilogue: per-query running max over this tile's 64 keys ----
        #pragma unroll
        for (int mt = 0; mt < 2; ++mt) {
            #pragma unroll
            for (int rh = 0; rh < 2; ++rh) {
                const int sl = mt * 2 + rh;
                float v = -3.4e38f;
                #pragma unroll
                for (int nt = 0; nt < 4; ++nt) {
                    v = fmaxf(v, acc[mt][nt][rh * 2 + 0]);
                    v = fmaxf(v, acc[mt][nt][rh * 2 + 1]);
                }
                v = fmaxf(v, __shfl_xor_sync(0xffffffffu, v, 1));
                v = fmaxf(v, __shfl_xor_sync(0xffffffffu, v, 2));
                if (qtr == 0) run_v[sl] = v;
                else          run_v[sl] = fmaxf(run_v[sl], v);
            }
        }

        if (qtr == 3) {
            if ((lane & 3) == 0) {
                #pragma unroll
                for (int mt = 0; mt < 2; ++mt)
                    #pragma unroll
                    for (int rh = 0; rh < 2; ++rh) {
                        int r = mbase + mt * 16 + rh * 8 + (lane >> 2);
                        xv[wn][r] = run_v[mt * 2 + rh];
                    }
            }
            __syncthreads();
            if (tid < 128)
                g_rowmax[(size_t)(q0 + tid) * NROWS + row] = fmaxf(xv[0][tid], xv[1][tid]);
            __syncthreads();
        }
    }
}

// ---------------------------------------------------------------------------
// Pass A2: threshold select — superset of top-64 rows per query.
// ---------------------------------------------------------------------------
__global__ void __launch_bounds__(256)
topsel_kernel()
{
    extern __shared__ uint32_t hist[];          // 8192 bins
    __shared__ int csum[256];
    __shared__ int s_binB;
    __shared__ int s_cc;

    const int q = blockIdx.x, tid = threadIdx.x;
    const float* src = g_rowmax + (size_t)q * NROWS;

    for (int i = tid; i < 8192; i += 256) hist[i] = 0;
    __syncthreads();

    for (int r = tid; r < NROWS; r += 256)
        atomicAdd(&hist[ford(src[r]) >> 19], 1u);
    __syncthreads();

    int local = 0;
    #pragma unroll
    for (int k = 0; k < 32; ++k) local += (int)hist[8191 - (32 * tid + k)];
    csum[tid] = local;
    __syncthreads();
    for (int off = 1; off < 256; off <<= 1) {
        int v = (tid >= off) ? csum[tid - off] : 0;
        __syncthreads();
        csum[tid] += v;
        __syncthreads();
    }
    int incl = csum[tid];
    int excl = incl - local;
    if (excl < 64 && incl >= 64) {
        int c = excl;
        for (int k = 0; k < 32; ++k) {
            c += (int)hist[8191 - (32 * tid + k)];
            if (c >= 64) { s_binB = 8191 - (32 * tid + k); break; }
        }
    }
    if (tid == 0) s_cc = 0;
    __syncthreads();

    const uint32_t binB = (uint32_t)s_binB;
    for (int r = tid; r < NROWS; r += 256) {
        if ((ford(src[r]) >> 19) >= binB) {
            int p = atomicAdd(&s_cc, 1);
            if (p < RCAP) g_cand[(size_t)q * RCAP + p] = r;
        }
    }
    __syncthreads();
    if (tid == 0) g_qcnt[q] = min(s_cc, RCAP);
}

// ---------------------------------------------------------------------------
__global__ void zero_kernel()
{
    int i = blockIdx.x * 256 + threadIdx.x;
    if (i < NROWS) g_rowcnt[i] = 0;
}

__global__ void __launch_bounds__(256)
scatter_kernel()
{
    const int q = blockIdx.x, slot = threadIdx.x;
    if (slot < g_qcnt[q]) {
        int row = g_cand[(size_t)q * RCAP + slot];
        int idx = atomicAdd(&g_rowcnt[row], 1);
        g_rowlist[(size_t)row * NQ + idx] = (q << 8) | slot;
    }
}

// ---------------------------------------------------------------------------
// Pass B: exact fp32 rescore; 2 CTAs per row, warp-per-entry (no CTA sync).
// ---------------------------------------------------------------------------
#define SMEM_R 65536

__global__ void __launch_bounds__(256)
rescore_kernel(const float* __restrict__ queries, const float* __restrict__ keys)
{
    const int row = blockIdx.x >> 1;
    const int h   = blockIdx.x & 1;
    const int cnt = g_rowcnt[row];
    if (cnt == 0) return;

    extern __shared__ __align__(1024) float Ks[];   // 128 keys x 128 dims fp32
    __shared__ unsigned long long s_mbar;

    const int tid  = threadIdx.x;
    const int lane = tid & 31;
    const int w    = tid >> 5;

    const uint32_t mbar = smem_u32(&s_mbar);
    if (tid == 0) MBARRIER_INIT(mbar, 1);
    __syncthreads();
    if (tid == 0) {
        MBARRIER_EXPECT_TX(mbar, 65536);
        bulk_g2s(smem_u32(Ks), keys + ((size_t)row * VPR + (size_t)h * 128) * DIM,
                 65536, mbar);
    }
    MBARRIER_WAIT_PARITY(mbar, 0);

    // warp w handles entries w, w+8, ... fully (dims across lanes)
    for (int i = w; i < cnt; i += 8) {
        const int e = g_rowlist[(size_t)row * NQ + i];
        const int q = e >> 8, slot = e & 255;

        float4 qv = *reinterpret_cast<const float4*>(queries + (size_t)q * DIM + lane * 4);

        unsigned long long best = 0ull;
        #pragma unroll 4
        for (int kl = 0; kl < 128; ++kl) {
            float4 kv = *reinterpret_cast<const float4*>(Ks + (size_t)kl * DIM + lane * 4);
            float d = qv.x * kv.x;
            d = fmaf(qv.y, kv.y, d);
            d = fmaf(qv.z, kv.z, d);
            d = fmaf(qv.w, kv.w, d);
            #pragma unroll
            for (int o = 16; o > 0; o >>= 1) d += __shfl_xor_sync(0xffffffffu, d, o);
            int gk = h * 128 + kl;
            unsigned long long p = ((unsigned long long)ford(d) << 32) | (uint32_t)(~gk);
            if (p > best) best = p;            // ascending gk -> tie keeps lowest
        }
        if (lane == 0) {
            size_t o = ((size_t)q * RCAP + slot) * 2 + h;
            g_exs2[o] = funord((uint32_t)(best >> 32));
            g_exa2[o] = (int)((uint8_t)(~(uint32_t)best));
        }
    }
}

// ---------------------------------------------------------------------------
// Pass C: merge halves, exact top-32, mask/softmax/gather outputs.
// ---------------------------------------------------------------------------
__device__ __forceinline__ void put(float* out, long long off, long long lim, float v) {
    if (off < lim) out[off] = v;
}

__global__ void __launch_bounds__(128)
finalize_kernel(const float* __restrict__ values, const int* __restrict__ mem_ids,
                const int* __restrict__ ent_ids, const int* __restrict__ text_ids,
                float* __restrict__ out, long long lim)
{
    volatile __shared__ float cs[RCAP];
    __shared__ int   cm[RCAP];
    __shared__ int   ca[RCAP];
    __shared__ int   ssel[KSEL];
    __shared__ float ssc[KSEL];
    __shared__ int   sid[KSEL];

    const int q = blockIdx.x, tid = threadIdx.x;
    const int cnt = g_qcnt[q];

    for (int s = tid; s < cnt; s += 128) {
        size_t o = ((size_t)q * RCAP + s) * 2;
        float s0 = g_exs2[o], s1 = g_exs2[o + 1];
        int   a0 = g_exa2[o], a1 = g_exa2[o + 1];
        float sc; int aa;
        if (s1 > s0) { sc = s1; aa = a1; } else { sc = s0; aa = a0; }
        cs[s] = sc;
        ca[s] = aa;
        cm[s] = (g_cand[(size_t)q * RCAP + s] << 8) | s;
    }
    __syncthreads();

    if (tid < 32) {
        for (int it = 0; it < KSEL; ++it) {
            float bv = -3.4e38f; int bm = 0x7FFFFFFF;
            #pragma unroll
            for (int k = 0; k < 8; ++k) {
                int s = tid + 32 * k;
                if (s < cnt) {
                    float v = cs[s]; int m = cm[s];
                    if (v > bv || (v == bv && m < bm)) { bv = v; bm = m; }
                }
            }
            #pragma unroll
            for (int o = 16; o > 0; o >>= 1) {
                float v2 = __shfl_xor_sync(0xffffffffu, bv, o);
                int   m2 = __shfl_xor_sync(0xffffffffu, bm, o);
                if (v2 > bv || (v2 == bv && m2 < bm)) { bv = v2; bm = m2; }
            }
            if (tid == 0) { ssel[it] = bm; ssc[it] = bv; cs[bm & 255] = -3.4e38f; }
            __syncwarp();
        }
    }
    __syncthreads();

    if (tid < KSEL) {
        int meta = ssel[tid];
        int slot = meta & 255, row = meta >> 8;
        float sc = ssc[tid];
        int   id = row * VPR + ca[slot];
        sid[tid] = id;

        int   m  = (mem_ids[id] == text_ids[q]) ? 1 : 0;
        float ms = sc - (float)m * 1e10f;

        float mx = ms;
        #pragma unroll
        for (int o = 16; o > 0; o >>= 1) mx = fmaxf(mx, __shfl_xor_sync(0xffffffffu, mx, o));
        float e = expf(ms - mx);
        float ssum = e;
        #pragma unroll
        for (int o = 16; o > 0; o >>= 1) ssum += __shfl_xor_sync(0xffffffffu, ssum, o);
        float wgt = e / ssum;

        int cdis = m;
        #pragma unroll
        for (int o = 16; o > 0; o >>= 1) cdis += __shfl_xor_sync(0xffffffffu, cdis, o);
        if (tid == 0) g_qdis[q] = cdis;

        long long base = (long long)q * KSEL + tid;
        put(out, OFF_ENT  + base, lim, (float)ent_ids[id]);
        put(out, OFF_GID  + base, lim, (float)id);
        put(out, OFF_SC   + base, lim, sc);
        put(out, OFF_MASK + base, lim, (float)m);
        put(out, OFF_ATTN + base, lim, wgt);
    }
    __syncthreads();

    for (int j = 0; j < KSEL; ++j) {
        int id = sid[j];
        long long o = OFF_VAL + ((long long)(q * KSEL + j)) * DIM + tid;
        if (o < lim) out[o] = values[(size_t)id * DIM + tid];
    }
}

// ---------------------------------------------------------------------------
__global__ void __launch_bounds__(512)
ndis_kernel(float* __restrict__ out, long long lim)
{
    __shared__ int s[512];
    int t = threadIdx.x;
    s[t] = g_qdis[t];
    __syncthreads();
    for (int st = 256; st > 0; st >>= 1) {
        if (t < st) s[t] += s[t + st];
        __syncthreads();
    }
    if (t == 0 && OFF_NDIS < lim) out[OFF_NDIS] = (float)s[0];
}

// ---------------------------------------------------------------------------
extern "C" void kernel_launch(void* const* d_in, const int* in_sizes, int n_in,
                              void* d_out, int out_size)
{
    const float* queries  = (const float*)d_in[0];
    const float* keys     = (const float*)d_in[1];
    const int*   mem_ids  = (const int*)d_in[2];
    const int*   ent_ids  = (const int*)d_in[3];
    const float* values   = (const float*)d_in[4];
    const int*   text_ids = (const int*)d_in[5];
    float* out = (float*)d_out;
    long long lim = (long long)out_size;

    cudaFuncSetAttribute(score_approx,   cudaFuncAttributeMaxDynamicSharedMemorySize, SMEM_A);
    cudaFuncSetAttribute(rescore_kernel, cudaFuncAttributeMaxDynamicSharedMemorySize, SMEM_R);
    cudaFuncSetAttribute(topsel_kernel,  cudaFuncAttributeMaxDynamicSharedMemorySize, 8192 * 4);

    score_approx<<<4 * GROUPS, 256, SMEM_A>>>(queries, keys);
    topsel_kernel<<<NQ, 256, 8192 * 4>>>();
    zero_kernel<<<(NROWS + 255) / 256, 256>>>();
    scatter_kernel<<<NQ, 256>>>();
    rescore_kernel<<<2 * NROWS, 256, SMEM_R>>>(queries, keys);
    finalize_kernel<<<NQ, 128>>>(values, mem_ids, ent_ids, text_ids, out, lim);
    ndis_kernel<<<1, 512>>>(out, lim);
}